// round 8
// baseline (speedup 1.0000x reference)
#include <cuda_runtime.h>

// B=32, T=256, E=512, H=512, 4H=2048
// inputs: x, fwd_Wih, fwd_bih, fwd_Whh, fwd_bhh, bwd_Wih, bwd_bih, bwd_Whh, bwd_bhh
// output: [B, T, 2H] fp32

typedef unsigned long long ULL;

__device__ float    g_xg[2][256][32][2048];   // projected gates (+folded biases)
__device__ float    g_h[2][2][512 * 32];      // [dir][buf][hcol*32 + b]
__device__ unsigned g_cnt[2];                 // per-direction barrier counters

__device__ __forceinline__ ULL fma2(ULL a, ULL b, ULL c) {
    ULL d; asm("fma.rn.f32x2 %0,%1,%2,%3;" : "=l"(d) : "l"(a), "l"(b), "l"(c)); return d;
}
__device__ __forceinline__ ULL add2(ULL a, ULL b) {
    ULL d; asm("add.rn.f32x2 %0,%1,%2;" : "=l"(d) : "l"(a), "l"(b)); return d;
}
__device__ __forceinline__ ULL dup2(float x) {
    ULL d; unsigned u = __float_as_uint(x);
    asm("mov.b64 %0,{%1,%1};" : "=l"(d) : "r"(u)); return d;
}
__device__ __forceinline__ ULL pack2(float lo, float hi) {
    ULL d; unsigned a = __float_as_uint(lo), b = __float_as_uint(hi);
    asm("mov.b64 %0,{%1,%2};" : "=l"(d) : "r"(a), "r"(b)); return d;
}

// ================= Kernel 1: input projection (both directions) ==================
// row m = dir*8192 + t*32 + b  (16384 rows), N = 2048, K = 512
// xg[m][n] = x[b][tsrc][:] . Wih[:][n] + bih[n] + bhh[n],  tsrc = t or 255-t
__global__ void __launch_bounds__(256) proj_kernel(
    const float* __restrict__ x,
    const float* __restrict__ Wf, const float* __restrict__ bf1, const float* __restrict__ bf2,
    const float* __restrict__ Wb, const float* __restrict__ bb1, const float* __restrict__ bb2)
{
    if (blockIdx.x == 0 && blockIdx.y == 0 && threadIdx.x == 0) { g_cnt[0] = 0u; g_cnt[1] = 0u; }

    __shared__ ULL   As[16][68];    // A tile, duplicated pairs, [k][m]
    __shared__ float Bs[16][128];   // B tile [k][n]

    const int t  = threadIdx.x;
    const int bn = blockIdx.x;      // 0..15
    const int bm = blockIdx.y;      // 0..255
    const int dir = bm >> 7;

    const int r  = t >> 2, kq = t & 3;       // A-load: row r, k-quarter kq
    const int m   = bm * 64 + r;
    const int rem = m & 8191;
    const int tt  = rem >> 5, bb = rem & 31;
    const int tsrc = dir ? (255 - tt) : tt;
    const float* xrow = x + ((long)bb * 256 + tsrc) * 512 + kq * 4;

    const float* W  = dir ? Wb : Wf;
    const float* Bp = W + (long)(t >> 5) * 2048 + bn * 128 + (t & 31) * 4;

    const int ty = t >> 4, tx = t & 15;      // compute: 16x16 grid, 4m x 8n micro

    ULL C[4][4] = {};

    for (int k0 = 0; k0 < 512; k0 += 16) {
        float4 av = *(const float4*)(xrow + k0);
        float4 b0 = *(const float4*)(Bp + (long)k0 * 2048);
        float4 b1 = *(const float4*)(Bp + (long)(k0 + 8) * 2048);
        __syncthreads();
        As[kq * 4 + 0][r] = dup2(av.x);
        As[kq * 4 + 1][r] = dup2(av.y);
        As[kq * 4 + 2][r] = dup2(av.z);
        As[kq * 4 + 3][r] = dup2(av.w);
        *(float4*)&Bs[(t >> 5)][(t & 31) * 4]     = b0;
        *(float4*)&Bs[(t >> 5) + 8][(t & 31) * 4] = b1;
        __syncthreads();
#pragma unroll
        for (int kk = 0; kk < 16; kk++) {
            ULL a0 = As[kk][ty * 4 + 0];
            ULL a1 = As[kk][ty * 4 + 1];
            ULL a2 = As[kk][ty * 4 + 2];
            ULL a3 = As[kk][ty * 4 + 3];
            const ULL* bp = (const ULL*)&Bs[kk][tx * 8];
            ULL q0 = bp[0], q1 = bp[1], q2 = bp[2], q3 = bp[3];
            C[0][0] = fma2(a0, q0, C[0][0]);  C[0][1] = fma2(a0, q1, C[0][1]);
            C[0][2] = fma2(a0, q2, C[0][2]);  C[0][3] = fma2(a0, q3, C[0][3]);
            C[1][0] = fma2(a1, q0, C[1][0]);  C[1][1] = fma2(a1, q1, C[1][1]);
            C[1][2] = fma2(a1, q2, C[1][2]);  C[1][3] = fma2(a1, q3, C[1][3]);
            C[2][0] = fma2(a2, q0, C[2][0]);  C[2][1] = fma2(a2, q1, C[2][1]);
            C[2][2] = fma2(a2, q2, C[2][2]);  C[2][3] = fma2(a2, q3, C[2][3]);
            C[3][0] = fma2(a3, q0, C[3][0]);  C[3][1] = fma2(a3, q1, C[3][1]);
            C[3][2] = fma2(a3, q2, C[3][2]);  C[3][3] = fma2(a3, q3, C[3][3]);
        }
    }

    // epilogue: add (bih + bhh), store
    const float* c1 = (dir ? bb1 : bf1) + bn * 128 + tx * 8;
    const float* c2 = (dir ? bb2 : bf2) + bn * 128 + tx * 8;
    ULL bias[4];
#pragma unroll
    for (int j = 0; j < 4; j++)
        bias[j] = pack2(c1[2 * j] + c2[2 * j], c1[2 * j + 1] + c2[2 * j + 1]);

    float* outbase = &g_xg[0][0][0][0];
#pragma unroll
    for (int i = 0; i < 4; i++) {
        long row = (long)(bm * 64 + ty * 4 + i);
        ULL* o = (ULL*)(outbase + row * 2048 + bn * 128 + tx * 8);
#pragma unroll
        for (int j = 0; j < 4; j++) o[j] = add2(C[i][j], bias[j]);
    }
}

// ================= Kernel 2: persistent recurrent scan ==================
// grid = 128 CTAs: dir = cta>>6, col-group cg = cta&63 owns h-cols [cg*8, cg*8+8)
// per step: G[b][c] = xg + h_prev @ Whh_slice  (B=32, N=32 gate cols, K=512),
// then gate nonlinearity, c-state update, h broadcast via L2 + flag barrier.
__global__ void __launch_bounds__(256, 1) scan_kernel(
    const float* __restrict__ Whf, const float* __restrict__ Whb, float* __restrict__ out)
{
    extern __shared__ float sm[];
    float* Ws = sm;            // [512][32]  Whh slice          (16384 floats)
    float* hs = sm + 16384;    // [512][32]  staged h_prev      (16384 floats)
    float* P  = sm + 32768;    // [8][32][36] K-split partials  ( 9216 floats)

    const int tid = threadIdx.x;
    const int cta = blockIdx.x;
    const int dir = cta >> 6;
    const int cg  = cta & 63;
    const int j0  = cg * 8;
    const float* Whh = dir ? Whb : Whf;

    // load Whh slice: Ws[k][c], c = G*8 + jj -> global col G*512 + j0 + jj
    for (int idx = tid; idx < 512 * 32; idx += 256) {
        int k = idx >> 5, c = idx & 31;
        Ws[idx] = Whh[(long)k * 2048 + (c >> 3) * 512 + j0 + (c & 7)];
    }
    // zero own h columns in buf 0 (one entry per thread: 8 cols x 32 b = 256)
    {
        int jj = tid >> 5, b = tid & 31;
        g_h[dir][0][(j0 + jj) * 32 + b] = 0.f;
    }
    __threadfence();
    __syncthreads();
    unsigned ep = 1;
    if (tid == 0) {
        atomicAdd(&g_cnt[dir], 1u);
        while (atomicAdd(&g_cnt[dir], 0u) < 64u * ep) {}
    }
    __syncthreads();

    // reduction/gate mapping: thread owns (b = tid>>3, jj = tid&7)
    const int rb = tid >> 3, rj = tid & 7;
    // GEMM mapping: 8 warps = K-split, lane -> 8b x 4n microtile
    const int w = tid >> 5, lane = tid & 31;
    const int b0 = (lane >> 3) * 8;     // 4 b-groups
    const int n0 = (lane & 7) * 4;      // 8 n-groups
    const int kbase = w * 64;

    float creg = 0.f;                   // cell state for (rb, rj)

    for (int s = 0; s < 256; s++) {
        const int rbuf = s & 1, wbuf = rbuf ^ 1;

        // prefetch xg gate values (consumed after GEMM -> latency hidden)
        const float* xgp = &g_xg[dir][s][rb][0];
        float xi = __ldg(&xgp[0 * 512 + j0 + rj]);
        float xf = __ldg(&xgp[1 * 512 + j0 + rj]);
        float xc = __ldg(&xgp[2 * 512 + j0 + rj]);
        float xo = __ldg(&xgp[3 * 512 + j0 + rj]);

        // stage h_prev (16384 floats) via L2 (L1 is stale within this kernel)
        const float4* hg = (const float4*)&g_h[dir][rbuf][0];
        float4* hsv = (float4*)hs;
#pragma unroll
        for (int i = 0; i < 16; i++)
            hsv[tid + i * 256] = __ldcg(hg + tid + i * 256);
        __syncthreads();

        // GEMM: acc[bi][n], ull pairs along batch
        ULL acc[4][4] = {};
#pragma unroll 4
        for (int kk = 0; kk < 64; kk++) {
            const int k = kbase + kk;
            const ULL* hp = (const ULL*)&hs[k * 32 + b0];
            ULL h0 = hp[0], h1 = hp[1], h2 = hp[2], h3 = hp[3];
            float4 wv = *(const float4*)&Ws[k * 32 + n0];
            ULL w0 = dup2(wv.x), w1 = dup2(wv.y), w2 = dup2(wv.z), w3 = dup2(wv.w);
            acc[0][0] = fma2(h0, w0, acc[0][0]);  acc[1][0] = fma2(h1, w0, acc[1][0]);
            acc[2][0] = fma2(h2, w0, acc[2][0]);  acc[3][0] = fma2(h3, w0, acc[3][0]);
            acc[0][1] = fma2(h0, w1, acc[0][1]);  acc[1][1] = fma2(h1, w1, acc[1][1]);
            acc[2][1] = fma2(h2, w1, acc[2][1]);  acc[3][1] = fma2(h3, w1, acc[3][1]);
            acc[0][2] = fma2(h0, w2, acc[0][2]);  acc[1][2] = fma2(h1, w2, acc[1][2]);
            acc[2][2] = fma2(h2, w2, acc[2][2]);  acc[3][2] = fma2(h3, w2, acc[3][2]);
            acc[0][3] = fma2(h0, w3, acc[0][3]);  acc[1][3] = fma2(h1, w3, acc[1][3]);
            acc[2][3] = fma2(h2, w3, acc[2][3]);  acc[3][3] = fma2(h3, w3, acc[3][3]);
        }

        // write partials: P[w][c][b], row stride 36 (even -> ULL-aligned, conflict-free reduce)
#pragma unroll
        for (int n = 0; n < 4; n++)
#pragma unroll
            for (int bi = 0; bi < 4; bi++)
                *(ULL*)&P[(w * 32 + n0 + n) * 36 + b0 + 2 * bi] = acc[bi][n];
        __syncthreads();

        // reduce K-split partials + gates for (rb, rj)
        float si = xi, sf = xf, sc = xc, so = xo;
#pragma unroll
        for (int ww = 0; ww < 8; ww++) {
            si += P[(ww * 32 +  0 + rj) * 36 + rb];
            sf += P[(ww * 32 +  8 + rj) * 36 + rb];
            sc += P[(ww * 32 + 16 + rj) * 36 + rb];
            so += P[(ww * 32 + 24 + rj) * 36 + rb];
        }
        float ig = 1.f / (1.f + __expf(-si));
        float fg = 1.f / (1.f + __expf(-sf));
        float gg = tanhf(sc);
        float og = 1.f / (1.f + __expf(-so));
        creg = fg * creg + ig * gg;
        float hv = og * tanhf(creg);

        // publish h (L2) + write output
        __stcg(&g_h[dir][wbuf][(j0 + rj) * 32 + rb], hv);
        out[((long)rb * 256 + s) * 1024 + dir * 512 + j0 + rj] = hv;

        __threadfence();
        __syncthreads();            // all stores done before the CTA arrives
        if (tid == 0) {
            ep++;
            atomicAdd(&g_cnt[dir], 1u);
            while (atomicAdd(&g_cnt[dir], 0u) < 64u * ep) {}
        }
        __syncthreads();
    }
}

extern "C" void kernel_launch(void* const* d_in, const int* in_sizes, int n_in,
                              void* d_out, int out_size)
{
    const float* x    = (const float*)d_in[0];
    const float* fWih = (const float*)d_in[1];
    const float* fbih = (const float*)d_in[2];
    const float* fWhh = (const float*)d_in[3];
    const float* fbhh = (const float*)d_in[4];
    const float* bWih = (const float*)d_in[5];
    const float* bbih = (const float*)d_in[6];
    const float* bWhh = (const float*)d_in[7];
    const float* bbhh = (const float*)d_in[8];
    float* out = (float*)d_out;

    const int smem = (16384 + 16384 + 9216) * 4;  // 167936 B
    cudaFuncSetAttribute(scan_kernel, cudaFuncAttributeMaxDynamicSharedMemorySize, smem);

    proj_kernel<<<dim3(16, 256), 256>>>(x, fWih, fbih, fbhh, bWih, bbih, bbhh);
    scan_kernel<<<128, 256, smem>>>(fWhh, bWhh, out);
}